// round 10
// baseline (speedup 1.0000x reference)
#include <cuda_runtime.h>
#include <math.h>

typedef unsigned long long ull;

// ---------------------------------------------------------------------------
// packed fp32x2 helpers (Blackwell FFMA2)
// ---------------------------------------------------------------------------
#define FMA2(d, a, b, c) \
    asm("fma.rn.f32x2 %0, %1, %2, %3;" : "=l"(d) : "l"(a), "l"(b), "l"(c))

static __device__ __forceinline__ ull pack2(float lo, float hi) {
    ull r; asm("mov.b64 %0, {%1, %2};" : "=l"(r) : "f"(lo), "f"(hi)); return r;
}
static __device__ __forceinline__ float2 unpack2(ull v) {
    float2 r; asm("mov.b64 {%0, %1}, %2;" : "=f"(r.x), "=f"(r.y) : "l"(v)); return r;
}
static __device__ __forceinline__ ull lds64(const float* p) {
    return *reinterpret_cast<const ull*>(p);
}

// Scratch: per-image softmax probabilities (1024 batches * 16 digits * 10)
__device__ float g_probs[1024 * 16 * 10];

// ---------------------------------------------------------------------------
// shared memory layout (float offsets)
// ---------------------------------------------------------------------------
#define OFF_DW1T  0        // [120][260]  transposed dw1, 16B-aligned rows
#define DW1_STR   260
#define OFF_DW2T  31200    // [84][124]   transposed dw2, 16B-aligned rows
#define DW2_STR   124
#define OFF_DW3   41616    // 840
#define OFF_W1P   42456    // [25][8]  conv1 weights, 6 ch + 2 pad per tap
#define OFF_W2X   42656    // 2400 interleaved conv2 weights
#define OFF_B1    45056    // 8
#define OFF_B2    45064    // 16
#define OFF_DB1   45080    // 120
#define OFF_DB2   45200    // 88
#define OFF_DB3   45288    // 12
#define OFF_IMG   45300    // [4][784]
#define OFF_P1T   48436    // [4][6][12][24]  pooled conv1, dup pairs
#define P1_IMG_STR 1728
#define OFF_P2    55348    // [4][264]
#define P2_STR    264
#define OFF_FC1   56404    // [4][120]
#define OFF_FC2   56884    // [4][88]
#define OFF_LOG   57236    // [4][12]
#define SMEM_FLOATS 57284  // = 229,136 bytes

#define QBAR() asm volatile("bar.sync %0, 128;" :: "r"(q + 1) : "memory")

// ---------------------------------------------------------------------------
// Phase bodies. rt = rotated role index within quarter (0..127),
// slot = this quarter's image slot (0..3).
// ---------------------------------------------------------------------------
__device__ __noinline__ void do_conv1(float* sm, int rt, int slot)
{
    if (rt >= 72) return;
    const int py = rt / 6, xg = rt % 6, x0 = 4 * xg;
    const float* ibase = sm + OFF_IMG + slot * 784 + 2 * py * 28 + x0;
    float* s_p1 = sm + OFF_P1T + slot * P1_IMG_STR;

    ull bp[3];
    #pragma unroll
    for (int cp = 0; cp < 3; cp++)
        bp[cp] = pack2(sm[OFF_B1 + 2 * cp], sm[OFF_B1 + 2 * cp + 1]);
    ull acc[2][4][3];
    #pragma unroll
    for (int dy = 0; dy < 2; dy++)
        #pragma unroll
        for (int dx = 0; dx < 4; dx++)
            #pragma unroll
            for (int cp = 0; cp < 3; cp++) acc[dy][dx][cp] = bp[cp];

    #pragma unroll
    for (int r = 0; r < 6; r++) {
        float4 v0 = *reinterpret_cast<const float4*>(ibase + r * 28);
        float4 v1 = *reinterpret_cast<const float4*>(ibase + r * 28 + 4);
        ull ap[8];
        ap[0] = pack2(v0.x, v0.x); ap[1] = pack2(v0.y, v0.y);
        ap[2] = pack2(v0.z, v0.z); ap[3] = pack2(v0.w, v0.w);
        ap[4] = pack2(v1.x, v1.x); ap[5] = pack2(v1.y, v1.y);
        ap[6] = pack2(v1.z, v1.z); ap[7] = pack2(v1.w, v1.w);
        #pragma unroll
        for (int dy = 0; dy < 2; dy++) {
            const int ky = r - dy;
            if (ky < 0 || ky > 4) continue;
            #pragma unroll
            for (int kx = 0; kx < 5; kx++) {
                const float* wp = sm + OFF_W1P + (ky * 5 + kx) * 8;
                ulonglong2 w01 = *reinterpret_cast<const ulonglong2*>(wp);
                ull w2 = lds64(wp + 4);
                #pragma unroll
                for (int dx = 0; dx < 4; dx++) {
                    FMA2(acc[dy][dx][0], ap[kx + dx], w01.x, acc[dy][dx][0]);
                    FMA2(acc[dy][dx][1], ap[kx + dx], w01.y, acc[dy][dx][1]);
                    FMA2(acc[dy][dx][2], ap[kx + dx], w2,    acc[dy][dx][2]);
                }
            }
        }
    }
    #pragma unroll
    for (int cp = 0; cp < 3; cp++) {
        #pragma unroll
        for (int dxp = 0; dxp < 2; dxp++) {
            float2 a0 = unpack2(acc[0][2 * dxp][cp]);
            float2 a1 = unpack2(acc[0][2 * dxp + 1][cp]);
            float2 b0 = unpack2(acc[1][2 * dxp][cp]);
            float2 b1 = unpack2(acc[1][2 * dxp + 1][cp]);
            float m0 = fmaxf(fmaxf(fmaxf(a0.x, a1.x), fmaxf(b0.x, b1.x)), 0.0f);
            float m1 = fmaxf(fmaxf(fmaxf(a0.y, a1.y), fmaxf(b0.y, b1.y)), 0.0f);
            const int px = 2 * xg + dxp;
            *reinterpret_cast<ull*>(s_p1 + ((2 * cp)     * 12 + py) * 24 + 2 * px) = pack2(m0, m0);
            *reinterpret_cast<ull*>(s_p1 + ((2 * cp + 1) * 12 + py) * 24 + 2 * px) = pack2(m1, m1);
        }
    }
}

__device__ __noinline__ void do_conv2(float* sm, int rt, int slot)
{
    // caller guarantees rt < 64. role = (py 0..3, xg 0..1, cg 0..7)
    const int py = rt >> 4, xg = (rt >> 3) & 1, cg = rt & 7;
    const int x0 = 4 * xg;
    const float* base0 = sm + OFF_P1T + slot * P1_IMG_STR + 2 * py * 24 + 2 * x0;
    const float* wbase = sm + OFF_W2X + cg * 4;

    ull bp = lds64(sm + OFF_B2 + 2 * cg);
    ull acc[2][4];
    #pragma unroll
    for (int dy = 0; dy < 2; dy++)
        #pragma unroll
        for (int dx = 0; dx < 4; dx++) acc[dy][dx] = bp;

    #pragma unroll
    for (int r = 0; r < 6; r++) {
        #pragma unroll
        for (int ip = 0; ip < 3; ip++) {
            const float* r0 = base0 + (2 * ip) * 288 + r * 24;
            const float* r1 = r0 + 288;
            ulonglong2 a00 = *reinterpret_cast<const ulonglong2*>(r0);
            ulonglong2 a01 = *reinterpret_cast<const ulonglong2*>(r0 + 4);
            ulonglong2 a02 = *reinterpret_cast<const ulonglong2*>(r0 + 8);
            ulonglong2 a03 = *reinterpret_cast<const ulonglong2*>(r0 + 12);
            ulonglong2 a10 = *reinterpret_cast<const ulonglong2*>(r1);
            ulonglong2 a11 = *reinterpret_cast<const ulonglong2*>(r1 + 4);
            ulonglong2 a12 = *reinterpret_cast<const ulonglong2*>(r1 + 8);
            ulonglong2 a13 = *reinterpret_cast<const ulonglong2*>(r1 + 12);
            ull ap0[8] = {a00.x, a00.y, a01.x, a01.y, a02.x, a02.y, a03.x, a03.y};
            ull ap1[8] = {a10.x, a10.y, a11.x, a11.y, a12.x, a12.y, a13.x, a13.y};
            #pragma unroll
            for (int dy = 0; dy < 2; dy++) {
                const int ky = r - dy;
                if (ky < 0 || ky > 4) continue;
                #pragma unroll
                for (int kx = 0; kx < 5; kx++) {
                    ulonglong2 w = *reinterpret_cast<const ulonglong2*>(
                        wbase + ((ky * 5 + kx) * 3 + ip) * 32);
                    #pragma unroll
                    for (int dx = 0; dx < 4; dx++) {
                        FMA2(acc[dy][dx], ap0[kx + dx], w.x, acc[dy][dx]);
                        FMA2(acc[dy][dx], ap1[kx + dx], w.y, acc[dy][dx]);
                    }
                }
            }
        }
    }
    float* s_p2 = sm + OFF_P2 + slot * P2_STR;
    #pragma unroll
    for (int dxp = 0; dxp < 2; dxp++) {
        float2 a0 = unpack2(acc[0][2 * dxp]);
        float2 a1 = unpack2(acc[0][2 * dxp + 1]);
        float2 b0 = unpack2(acc[1][2 * dxp]);
        float2 b1 = unpack2(acc[1][2 * dxp + 1]);
        float m0 = fmaxf(fmaxf(fmaxf(a0.x, a1.x), fmaxf(b0.x, b1.x)), 0.0f);
        float m1 = fmaxf(fmaxf(fmaxf(a0.y, a1.y), fmaxf(b0.y, b1.y)), 0.0f);
        const int px = 2 * xg + dxp;
        *reinterpret_cast<ull*>(s_p2 + (py * 4 + px) * 16 + 2 * cg) = pack2(m0, m1);
    }
}

static __device__ __forceinline__ void do_fc1(float* sm, int rt, int slot)
{
    if (rt >= 120) return;
    const float* act = sm + OFF_P2 + slot * P2_STR;
    const float* wr  = sm + OFF_DW1T + rt * DW1_STR;
    ull acc0 = pack2(0.0f, 0.0f), acc1 = pack2(0.0f, 0.0f);
    #pragma unroll 8
    for (int k = 0; k < 256; k += 4) {
        ulonglong2 av = *reinterpret_cast<const ulonglong2*>(act + k);
        ulonglong2 wv = *reinterpret_cast<const ulonglong2*>(wr + k);
        FMA2(acc0, av.x, wv.x, acc0);
        FMA2(acc1, av.y, wv.y, acc1);
    }
    float2 s0 = unpack2(acc0), s1 = unpack2(acc1);
    float v = s0.x + s0.y + s1.x + s1.y + sm[OFF_DB1 + rt];
    sm[OFF_FC1 + slot * 120 + rt] = fmaxf(v, 0.0f);
}

static __device__ __forceinline__ void do_fc2(float* sm, int rt, int slot)
{
    if (rt >= 84) return;
    const float* act = sm + OFF_FC1 + slot * 120;
    const float* wr  = sm + OFF_DW2T + rt * DW2_STR;
    ull acc0 = pack2(0.0f, 0.0f), acc1 = pack2(0.0f, 0.0f);
    #pragma unroll 6
    for (int k = 0; k < 120; k += 4) {
        ulonglong2 av = *reinterpret_cast<const ulonglong2*>(act + k);
        ulonglong2 wv = *reinterpret_cast<const ulonglong2*>(wr + k);
        FMA2(acc0, av.x, wv.x, acc0);
        FMA2(acc1, av.y, wv.y, acc1);
    }
    float2 s0 = unpack2(acc0), s1 = unpack2(acc1);
    float v = s0.x + s0.y + s1.x + s1.y + sm[OFF_DB2 + rt];
    sm[OFF_FC2 + slot * 88 + rt] = fmaxf(v, 0.0f);
}

// fc3 + softmax fused: roles 0..31 are one physical warp (rt = (t+32q)&127
// maps rt 0..31 to a contiguous aligned 32-thread group). No named barrier
// between fc3 and softmax — just __syncwarp.
static __device__ __forceinline__ void do_fc3_softmax(float* sm, int rt, int slot,
                                                      int img, int nimg)
{
    if (rt >= 32) return;
    if (rt < 10) {
        const float* act = sm + OFF_FC2 + slot * 88;
        float acc = sm[OFF_DB3 + rt];
        #pragma unroll 4
        for (int k = 0; k < 84; k++)
            acc = fmaf(act[k], sm[OFF_DW3 + k * 10 + rt], acc);
        sm[OFF_LOG + slot * 12 + rt] = acc;
    }
    __syncwarp();
    if (rt == 0 && img < nimg) {
        const float* lg = sm + OFF_LOG + slot * 12;
        float mx = lg[0];
        #pragma unroll
        for (int j = 1; j < 10; j++) mx = fmaxf(mx, lg[j]);
        float e[10], s = 0.0f;
        #pragma unroll
        for (int j = 0; j < 10; j++) { e[j] = __expf(lg[j] - mx); s += e[j]; }
        float inv = 1.0f / s;
        float* po = g_probs + (size_t)img * 10;
        #pragma unroll
        for (int j = 0; j < 10; j++) po[j] = e[j] * inv;
    }
}

static __device__ __forceinline__ void do_prefetch(float* sm, int rt, int slot,
                                                   const float* inputs,
                                                   int nb, int nimg)
{
    // roles 64..127 copy this quarter's next image
    const int i0 = rt - 64;
    if (nb < nimg) {
        const float4* iv = reinterpret_cast<const float4*>(inputs + (size_t)nb * 784);
        float4* ov = reinterpret_cast<float4*>(sm + OFF_IMG + slot * 784);
        #pragma unroll
        for (int i = i0; i < 196; i += 64) ov[i] = iv[i];
    }
}

// ---------------------------------------------------------------------------
// Kernel 1: persistent fused LeNet. 148 CTAs x 512 threads; FOUR independent
// 128-thread quarters (quarter q = warps 4q..4q+3 -> one warp per SMSP each),
// one image in flight per quarter, staggered prologue offsets so each SMSP
// holds 4 warps in 4 different phases at steady state.
// ---------------------------------------------------------------------------
__global__ void __launch_bounds__(512, 1) cnn_kernel(
    const float* __restrict__ inputs,
    const float* __restrict__ cw1, const float* __restrict__ cb1,
    const float* __restrict__ cw2, const float* __restrict__ cb2,
    const float* __restrict__ dw1, const float* __restrict__ db1,
    const float* __restrict__ dw2, const float* __restrict__ db2,
    const float* __restrict__ dw3, const float* __restrict__ db3,
    int nimg)
{
    extern __shared__ float sm[];
    const int tid = threadIdx.x;

    // ---- one-time weight staging ----
    for (int idx = tid; idx < 256 * 120; idx += 512) {
        int k = idx / 120, j = idx % 120;
        sm[OFF_DW1T + j * DW1_STR + k] = dw1[idx];
    }
    for (int idx = tid; idx < 120 * 84; idx += 512) {
        int k = idx / 84, j = idx % 84;
        sm[OFF_DW2T + j * DW2_STR + k] = dw2[idx];
    }
    for (int idx = tid; idx < 840; idx += 512) sm[OFF_DW3 + idx] = dw3[idx];
    for (int idx = tid; idx < 150; idx += 512) {
        int pk = idx / 6, c = idx % 6;
        sm[OFF_W1P + pk * 8 + c] = cw1[idx];
    }
    for (int idx = tid; idx < 2400; idx += 512) {
        int p = idx >> 4, ch = idx & 15;
        int pk = p / 6, i = p % 6;
        sm[OFF_W2X + (pk * 3 + (i >> 1)) * 32 + (ch >> 1) * 4 + (i & 1) * 2 + (ch & 1)]
            = cw2[idx];
    }
    if (tid < 6)   sm[OFF_B1  + tid] = cb1[tid];
    if (tid < 16)  sm[OFF_B2  + tid] = cb2[tid];
    if (tid < 120) sm[OFF_DB1 + tid] = db1[tid];
    if (tid < 84)  sm[OFF_DB2 + tid] = db2[tid];
    if (tid < 10)  sm[OFF_DB3 + tid] = db3[tid];

    // ---- prologue: load first 4 images (guarded) ----
    {
        const int b0 = blockIdx.x * 4;
        #pragma unroll
        for (int k = 0; k < 4; k++) {
            if (b0 + k < nimg) {
                const float4* iv = reinterpret_cast<const float4*>(inputs + (size_t)(b0 + k) * 784);
                float4* ov = reinterpret_cast<float4*>(sm + OFF_IMG + k * 784);
                for (int i = tid; i < 196; i += 512) ov[i] = iv[i];
            }
        }
    }
    __syncthreads();

    const int q  = tid >> 7;                 // quarter 0..3
    const int t  = tid & 127;
    const int rt = (t + (q << 5)) & 127;     // rotated role index
    const int slot = q;
    const int qstep = gridDim.x * 4;

    // ---- staggered phase offsets: quarter q does q dummy conv1 passes ----
    for (int k = 0; k < q; k++) {
        do_conv1(sm, rt, slot);
        QBAR();
    }

    for (int img = blockIdx.x * 4 + q; img < nimg; img += qstep) {
        do_conv1(sm, rt, slot);
        QBAR();
        if (rt < 64) do_conv2(sm, rt, slot);
        else         do_prefetch(sm, rt, slot, inputs, img + qstep, nimg);
        QBAR();
        do_fc1(sm, rt, slot);
        QBAR();
        do_fc2(sm, rt, slot);
        QBAR();
        do_fc3_softmax(sm, rt, slot, img, nimg);
        QBAR();
    }
}

// ---------------------------------------------------------------------------
// Kernel 2: Luhn DP (register-resident, high-MLP loads).
// ---------------------------------------------------------------------------
template <int N>
__device__ __forceinline__ float luhn_eval(const float* __restrict__ p)
{
    const int LUHN[10] = {0, 5, 1, 6, 2, 7, 3, 8, 4, 9};
    float4 v[(N * 10) / 4];
    const float4* pv = reinterpret_cast<const float4*>(p);
    #pragma unroll
    for (int i = 0; i < (N * 10) / 4; i++) v[i] = pv[i];
    float d[N * 10];
    #pragma unroll
    for (int i = 0; i < (N * 10) / 4; i++) {
        d[4 * i] = v[i].x; d[4 * i + 1] = v[i].y;
        d[4 * i + 2] = v[i].z; d[4 * i + 3] = v[i].w;
    }
    const int m = N - 1;
    float cur[10];
    #pragma unroll
    for (int j = 0; j < 10; j++)
        cur[j] = ((0 % 2) == (m % 2)) ? d[10 + LUHN[j]] : d[10 + j];
    #pragma unroll
    for (int i = 1; i < m; i++) {
        float dd[10];
        #pragma unroll
        for (int j = 0; j < 10; j++)
            dd[j] = ((i % 2) == (m % 2)) ? d[(i + 1) * 10 + LUHN[j]] : d[(i + 1) * 10 + j];
        float nxt[10];
        #pragma unroll
        for (int s = 0; s < 10; s++) nxt[s] = 0.0f;
        #pragma unroll
        for (int a = 0; a < 10; a++)
            #pragma unroll
            for (int qd = 0; qd < 10; qd++)
                nxt[(a + qd) % 10] = fmaf(cur[a], dd[qd], nxt[(a + qd) % 10]);
        #pragma unroll
        for (int s = 0; s < 10; s++) cur[s] = nxt[s];
    }
    float t10 = 0.0f;
    #pragma unroll
    for (int a = 1; a < 10; a++) t10 = fmaf(d[a], cur[10 - a], t10);
    return logf(t10);
}

__device__ float luhn_generic(const float* __restrict__ p, int n)
{
    const int LUHN[10] = {0, 5, 1, 6, 2, 7, 3, 8, 4, 9};
    const int m = n - 1;
    float cur[10];
    {
        const float* d = p + 10;
        bool perm = ((0 & 1) == (m & 1));
        #pragma unroll
        for (int j = 0; j < 10; j++) cur[j] = perm ? d[LUHN[j]] : d[j];
    }
    for (int i = 1; i < m; i++) {
        const float* d = p + (size_t)(i + 1) * 10;
        bool perm = ((i & 1) == (m & 1));
        float dd[10];
        #pragma unroll
        for (int j = 0; j < 10; j++) dd[j] = perm ? d[LUHN[j]] : d[j];
        float nxt[10];
        #pragma unroll
        for (int s = 0; s < 10; s++) nxt[s] = 0.0f;
        #pragma unroll
        for (int a = 0; a < 10; a++)
            #pragma unroll
            for (int qd = 0; qd < 10; qd++)
                nxt[(a + qd) % 10] = fmaf(cur[a], dd[qd], nxt[(a + qd) % 10]);
        #pragma unroll
        for (int s = 0; s < 10; s++) cur[s] = nxt[s];
    }
    float t10 = 0.0f;
    #pragma unroll
    for (int a = 1; a < 10; a++) t10 = fmaf(p[a], cur[10 - a], t10);
    return logf(t10);
}

__global__ void luhn_kernel(float* __restrict__ out, int B, int n)
{
    int b = blockIdx.x * blockDim.x + threadIdx.x;
    if (b >= B) return;
    const float* p = g_probs + (size_t)b * n * 10;
    if (n == 16) out[b] = luhn_eval<16>(p);
    else         out[b] = luhn_generic(p, n);
}

// ---------------------------------------------------------------------------
extern "C" void kernel_launch(void* const* d_in, const int* in_sizes, int n_in,
                              void* d_out, int out_size)
{
    const float* inputs = (const float*)d_in[0];
    const float* cw1    = (const float*)d_in[1];
    const float* cb1    = (const float*)d_in[2];
    const float* cw2    = (const float*)d_in[3];
    const float* cb2    = (const float*)d_in[4];
    const float* dw1    = (const float*)d_in[5];
    const float* db1    = (const float*)d_in[6];
    const float* dw2    = (const float*)d_in[7];
    const float* db2    = (const float*)d_in[8];
    const float* dw3    = (const float*)d_in[9];
    const float* db3    = (const float*)d_in[10];
    float* out = (float*)d_out;

    const int B = out_size;                      // 1024
    const int n = in_sizes[0] / (B * 784);       // 16
    const int nimg = B * n;

    const size_t smem_bytes = SMEM_FLOATS * sizeof(float);  // 229,136 B
    cudaFuncSetAttribute(cnn_kernel, cudaFuncAttributeMaxDynamicSharedMemorySize,
                         (int)smem_bytes);

    cnn_kernel<<<148, 512, smem_bytes>>>(inputs, cw1, cb1, cw2, cb2,
                                         dw1, db1, dw2, db2, dw3, db3, nimg);
    luhn_kernel<<<(B + 127) / 128, 128>>>(out, B, n);
}

// round 11
// speedup vs baseline: 1.1907x; 1.1907x over previous
#include <cuda_runtime.h>
#include <math.h>

typedef unsigned long long ull;

// ---------------------------------------------------------------------------
// packed fp32x2 helpers (Blackwell FFMA2)
// ---------------------------------------------------------------------------
#define FMA2(d, a, b, c) \
    asm("fma.rn.f32x2 %0, %1, %2, %3;" : "=l"(d) : "l"(a), "l"(b), "l"(c))

static __device__ __forceinline__ ull pack2(float lo, float hi) {
    ull r; asm("mov.b64 %0, {%1, %2};" : "=l"(r) : "f"(lo), "f"(hi)); return r;
}
static __device__ __forceinline__ float2 unpack2(ull v) {
    float2 r; asm("mov.b64 {%0, %1}, %2;" : "=f"(r.x), "=f"(r.y) : "l"(v)); return r;
}
static __device__ __forceinline__ ull lds64(const float* p) {
    return *reinterpret_cast<const ull*>(p);
}

// Scratch: per-image softmax probabilities (1024 batches * 16 digits * 10)
__device__ float g_probs[1024 * 16 * 10];

// ---------------------------------------------------------------------------
// shared memory layout (float offsets)
// ---------------------------------------------------------------------------
#define OFF_DW1T  0        // [120][260]  transposed dw1, 16B-aligned rows
#define DW1_STR   260
#define OFF_DW2T  31200    // [84][124]   transposed dw2, 16B-aligned rows
#define DW2_STR   124
#define OFF_DW3   41616    // 840
#define OFF_W1P   42456    // [25][8]  conv1 weights, 6 ch + 2 pad per tap
#define OFF_W2X   42656    // 2400 interleaved conv2 weights
#define OFF_B1    45056    // 8
#define OFF_B2    45064    // 16
#define OFF_DB1   45080    // 120
#define OFF_DB2   45200    // 88
#define OFF_DB3   45288    // 12
#define OFF_IMG   45300    // [4][784]
#define OFF_P1T   48436    // [4][6][12][24]  pooled conv1, dup pairs
#define P1_IMG_STR 1728
#define OFF_P2    55348    // [4][264]
#define P2_STR    264
#define OFF_FC1   56404    // [4][120]
#define OFF_FC2   56884    // [4][88]
#define OFF_LOG   57236    // [4][12]
#define SMEM_FLOATS 57284  // = 229,136 bytes

// barriers: ids 1/2 = full half (256), ids 5/6 = fc group (96)
#define HBAR(h) asm volatile("bar.sync %0, 256;" :: "r"((h) + 1) : "memory")
#define FBAR(h) asm volatile("bar.sync %0, 96;"  :: "r"((h) + 5) : "memory")

// ---------------------------------------------------------------------------
// Phase bodies. t = thread index within half (0..255). slot0 = 2*half.
// ---------------------------------------------------------------------------
__device__ __noinline__ void do_conv1_pair(float* sm, int t, int slot0)
{
    if (t >= 144) return;
    const int im  = t / 72;
    const int r72 = t % 72;
    const int py = r72 / 6, xg = r72 % 6, x0 = 4 * xg;
    const float* ibase = sm + OFF_IMG + (slot0 + im) * 784 + 2 * py * 28 + x0;
    float* s_p1 = sm + OFF_P1T + (slot0 + im) * P1_IMG_STR;

    ull bp[3];
    #pragma unroll
    for (int cp = 0; cp < 3; cp++)
        bp[cp] = pack2(sm[OFF_B1 + 2 * cp], sm[OFF_B1 + 2 * cp + 1]);
    ull acc[2][4][3];
    #pragma unroll
    for (int dy = 0; dy < 2; dy++)
        #pragma unroll
        for (int dx = 0; dx < 4; dx++)
            #pragma unroll
            for (int cp = 0; cp < 3; cp++) acc[dy][dx][cp] = bp[cp];

    #pragma unroll
    for (int r = 0; r < 6; r++) {
        float4 v0 = *reinterpret_cast<const float4*>(ibase + r * 28);
        float4 v1 = *reinterpret_cast<const float4*>(ibase + r * 28 + 4);
        ull ap[8];
        ap[0] = pack2(v0.x, v0.x); ap[1] = pack2(v0.y, v0.y);
        ap[2] = pack2(v0.z, v0.z); ap[3] = pack2(v0.w, v0.w);
        ap[4] = pack2(v1.x, v1.x); ap[5] = pack2(v1.y, v1.y);
        ap[6] = pack2(v1.z, v1.z); ap[7] = pack2(v1.w, v1.w);
        #pragma unroll
        for (int dy = 0; dy < 2; dy++) {
            const int ky = r - dy;
            if (ky < 0 || ky > 4) continue;
            #pragma unroll
            for (int kx = 0; kx < 5; kx++) {
                const float* wp = sm + OFF_W1P + (ky * 5 + kx) * 8;
                ulonglong2 w01 = *reinterpret_cast<const ulonglong2*>(wp);
                ull w2 = lds64(wp + 4);
                #pragma unroll
                for (int dx = 0; dx < 4; dx++) {
                    FMA2(acc[dy][dx][0], ap[kx + dx], w01.x, acc[dy][dx][0]);
                    FMA2(acc[dy][dx][1], ap[kx + dx], w01.y, acc[dy][dx][1]);
                    FMA2(acc[dy][dx][2], ap[kx + dx], w2,    acc[dy][dx][2]);
                }
            }
        }
    }
    #pragma unroll
    for (int cp = 0; cp < 3; cp++) {
        #pragma unroll
        for (int dxp = 0; dxp < 2; dxp++) {
            float2 a0 = unpack2(acc[0][2 * dxp][cp]);
            float2 a1 = unpack2(acc[0][2 * dxp + 1][cp]);
            float2 b0 = unpack2(acc[1][2 * dxp][cp]);
            float2 b1 = unpack2(acc[1][2 * dxp + 1][cp]);
            float m0 = fmaxf(fmaxf(fmaxf(a0.x, a1.x), fmaxf(b0.x, b1.x)), 0.0f);
            float m1 = fmaxf(fmaxf(fmaxf(a0.y, a1.y), fmaxf(b0.y, b1.y)), 0.0f);
            const int px = 2 * xg + dxp;
            *reinterpret_cast<ull*>(s_p1 + ((2 * cp)     * 12 + py) * 24 + 2 * px) = pack2(m0, m0);
            *reinterpret_cast<ull*>(s_p1 + ((2 * cp + 1) * 12 + py) * 24 + 2 * px) = pack2(m1, m1);
        }
    }
}

__device__ __noinline__ void do_conv2(float* sm, int t, int slot0)
{
    // caller guarantees t < 128. thread = (im, py 0..3, xg 0..1, cg 0..7)
    const int im = t >> 6;
    const int u  = t & 63;
    const int py = u >> 4, xg = (u >> 3) & 1, cg = u & 7;
    const int x0 = 4 * xg;
    const float* base0 = sm + OFF_P1T + (slot0 + im) * P1_IMG_STR + 2 * py * 24 + 2 * x0;
    const float* wbase = sm + OFF_W2X + cg * 4;

    ull bp = lds64(sm + OFF_B2 + 2 * cg);
    ull acc[2][4];
    #pragma unroll
    for (int dy = 0; dy < 2; dy++)
        #pragma unroll
        for (int dx = 0; dx < 4; dx++) acc[dy][dx] = bp;

    #pragma unroll
    for (int r = 0; r < 6; r++) {
        #pragma unroll
        for (int ip = 0; ip < 3; ip++) {
            const float* r0 = base0 + (2 * ip) * 288 + r * 24;
            const float* r1 = r0 + 288;
            ulonglong2 a00 = *reinterpret_cast<const ulonglong2*>(r0);
            ulonglong2 a01 = *reinterpret_cast<const ulonglong2*>(r0 + 4);
            ulonglong2 a02 = *reinterpret_cast<const ulonglong2*>(r0 + 8);
            ulonglong2 a03 = *reinterpret_cast<const ulonglong2*>(r0 + 12);
            ulonglong2 a10 = *reinterpret_cast<const ulonglong2*>(r1);
            ulonglong2 a11 = *reinterpret_cast<const ulonglong2*>(r1 + 4);
            ulonglong2 a12 = *reinterpret_cast<const ulonglong2*>(r1 + 8);
            ulonglong2 a13 = *reinterpret_cast<const ulonglong2*>(r1 + 12);
            ull ap0[8] = {a00.x, a00.y, a01.x, a01.y, a02.x, a02.y, a03.x, a03.y};
            ull ap1[8] = {a10.x, a10.y, a11.x, a11.y, a12.x, a12.y, a13.x, a13.y};
            #pragma unroll
            for (int dy = 0; dy < 2; dy++) {
                const int ky = r - dy;
                if (ky < 0 || ky > 4) continue;
                #pragma unroll
                for (int kx = 0; kx < 5; kx++) {
                    ulonglong2 w = *reinterpret_cast<const ulonglong2*>(
                        wbase + ((ky * 5 + kx) * 3 + ip) * 32);
                    #pragma unroll
                    for (int dx = 0; dx < 4; dx++) {
                        FMA2(acc[dy][dx], ap0[kx + dx], w.x, acc[dy][dx]);
                        FMA2(acc[dy][dx], ap1[kx + dx], w.y, acc[dy][dx]);
                    }
                }
            }
        }
    }
    float* s_p2 = sm + OFF_P2 + (slot0 + im) * P2_STR;
    #pragma unroll
    for (int dxp = 0; dxp < 2; dxp++) {
        float2 a0 = unpack2(acc[0][2 * dxp]);
        float2 a1 = unpack2(acc[0][2 * dxp + 1]);
        float2 b0 = unpack2(acc[1][2 * dxp]);
        float2 b1 = unpack2(acc[1][2 * dxp + 1]);
        float m0 = fmaxf(fmaxf(fmaxf(a0.x, a1.x), fmaxf(b0.x, b1.x)), 0.0f);
        float m1 = fmaxf(fmaxf(fmaxf(a0.y, a1.y), fmaxf(b0.y, b1.y)), 0.0f);
        const int px = 2 * xg + dxp;
        *reinterpret_cast<ull*>(s_p2 + (py * 4 + px) * 16 + 2 * cg) = pack2(m0, m1);
    }
}

// fc chain on 96 threads (warps 5-7 of the half). tF = t - 160 (0..95).
// fc1: 240 units (j 0..119, im 0..1); u = tF + 96k keeps lane-pair weight dedup.
static __device__ __forceinline__ void do_fc1_96(float* sm, int tF, int slot0)
{
    for (int u = tF; u < 240; u += 96) {
        const int j = u >> 1, im = u & 1;
        const float* act = sm + OFF_P2 + (slot0 + im) * P2_STR;
        const float* wr  = sm + OFF_DW1T + j * DW1_STR;
        ull acc0 = pack2(0.0f, 0.0f), acc1 = pack2(0.0f, 0.0f);
        #pragma unroll 8
        for (int k = 0; k < 256; k += 4) {
            ulonglong2 av = *reinterpret_cast<const ulonglong2*>(act + k);
            ulonglong2 wv = *reinterpret_cast<const ulonglong2*>(wr + k);
            FMA2(acc0, av.x, wv.x, acc0);
            FMA2(acc1, av.y, wv.y, acc1);
        }
        float2 s0 = unpack2(acc0), s1 = unpack2(acc1);
        float v = s0.x + s0.y + s1.x + s1.y + sm[OFF_DB1 + j];
        sm[OFF_FC1 + (slot0 + im) * 120 + j] = fmaxf(v, 0.0f);
    }
}

static __device__ __forceinline__ void do_fc2_96(float* sm, int tF, int slot0)
{
    for (int u = tF; u < 168; u += 96) {
        const int j = u >> 1, im = u & 1;
        const float* act = sm + OFF_FC1 + (slot0 + im) * 120;
        const float* wr  = sm + OFF_DW2T + j * DW2_STR;
        ull acc0 = pack2(0.0f, 0.0f), acc1 = pack2(0.0f, 0.0f);
        #pragma unroll 6
        for (int k = 0; k < 120; k += 4) {
            ulonglong2 av = *reinterpret_cast<const ulonglong2*>(act + k);
            ulonglong2 wv = *reinterpret_cast<const ulonglong2*>(wr + k);
            FMA2(acc0, av.x, wv.x, acc0);
            FMA2(acc1, av.y, wv.y, acc1);
        }
        float2 s0 = unpack2(acc0), s1 = unpack2(acc1);
        float v = s0.x + s0.y + s1.x + s1.y + sm[OFF_DB2 + j];
        sm[OFF_FC2 + (slot0 + im) * 88 + j] = fmaxf(v, 0.0f);
    }
}

// fc3 (20 units) + softmax (2 units), all inside warp 5 (tF 0..31).
static __device__ __forceinline__ void do_fc3_softmax_96(float* sm, int tF, int slot0,
                                                         int img0, int nimg)
{
    if (tF >= 32) return;
    if (tF < 20) {
        const int j = tF >> 1, im = tF & 1;
        const float* act = sm + OFF_FC2 + (slot0 + im) * 88;
        float acc = sm[OFF_DB3 + j];
        #pragma unroll 4
        for (int k = 0; k < 84; k++)
            acc = fmaf(act[k], sm[OFF_DW3 + k * 10 + j], acc);
        sm[OFF_LOG + (slot0 + im) * 12 + j] = acc;
    }
    __syncwarp();
    if (tF < 2) {
        const int img = img0 + tF;
        if (img < nimg) {
            const float* lg = sm + OFF_LOG + (slot0 + tF) * 12;
            float mx = lg[0];
            #pragma unroll
            for (int j = 1; j < 10; j++) mx = fmaxf(mx, lg[j]);
            float e[10], s = 0.0f;
            #pragma unroll
            for (int j = 0; j < 10; j++) { e[j] = __expf(lg[j] - mx); s += e[j]; }
            float inv = 1.0f / s;
            float* po = g_probs + (size_t)img * 10;
            #pragma unroll
            for (int j = 0; j < 10; j++) po[j] = e[j] * inv;
        }
    }
}

static __device__ __forceinline__ void do_prefetch(float* sm, int t, int slot0,
                                                   const float* inputs,
                                                   int nb, int nimg)
{
    // threads t in [128,256): copy this half's next 2 images
    const int i0 = t - 128;
    if (nb + slot0 < nimg) {
        const float4* iv = reinterpret_cast<const float4*>(inputs + (size_t)(nb + slot0) * 784);
        float4* ov = reinterpret_cast<float4*>(sm + OFF_IMG + slot0 * 784);
        for (int i = i0; i < 196; i += 128) ov[i] = iv[i];
    }
    if (nb + slot0 + 1 < nimg) {
        const float4* iv = reinterpret_cast<const float4*>(inputs + (size_t)(nb + slot0 + 1) * 784);
        float4* ov = reinterpret_cast<float4*>(sm + OFF_IMG + (slot0 + 1) * 784);
        for (int i = i0; i < 196; i += 128) ov[i] = iv[i];
    }
}

// ---------------------------------------------------------------------------
// Kernel 1: persistent fused LeNet. 148 CTAs x 512 threads; two independent
// 256-thread halves, each a 2-stage software pipeline over pairs of images:
//   P1: conv2(cur) || prefetch(next)
//   P2: conv1(next) [warps 0-4]  ||  fc1->fc2->fc3->softmax(cur) [warps 5-7]
// ---------------------------------------------------------------------------
__global__ void __launch_bounds__(512, 1) cnn_kernel(
    const float* __restrict__ inputs,
    const float* __restrict__ cw1, const float* __restrict__ cb1,
    const float* __restrict__ cw2, const float* __restrict__ cb2,
    const float* __restrict__ dw1, const float* __restrict__ db1,
    const float* __restrict__ dw2, const float* __restrict__ db2,
    const float* __restrict__ dw3, const float* __restrict__ db3,
    int nimg)
{
    extern __shared__ float sm[];
    const int tid = threadIdx.x;

    // ---- one-time weight staging ----
    for (int idx = tid; idx < 256 * 120; idx += 512) {
        int k = idx / 120, j = idx % 120;
        sm[OFF_DW1T + j * DW1_STR + k] = dw1[idx];
    }
    for (int idx = tid; idx < 120 * 84; idx += 512) {
        int k = idx / 84, j = idx % 84;
        sm[OFF_DW2T + j * DW2_STR + k] = dw2[idx];
    }
    for (int idx = tid; idx < 840; idx += 512) sm[OFF_DW3 + idx] = dw3[idx];
    for (int idx = tid; idx < 150; idx += 512) {
        int pk = idx / 6, c = idx % 6;
        sm[OFF_W1P + pk * 8 + c] = cw1[idx];
    }
    for (int idx = tid; idx < 2400; idx += 512) {
        int p = idx >> 4, ch = idx & 15;
        int pk = p / 6, i = p % 6;
        sm[OFF_W2X + (pk * 3 + (i >> 1)) * 32 + (ch >> 1) * 4 + (i & 1) * 2 + (ch & 1)]
            = cw2[idx];
    }
    if (tid < 6)   sm[OFF_B1  + tid] = cb1[tid];
    if (tid < 16)  sm[OFF_B2  + tid] = cb2[tid];
    if (tid < 120) sm[OFF_DB1 + tid] = db1[tid];
    if (tid < 84)  sm[OFF_DB2 + tid] = db2[tid];
    if (tid < 10)  sm[OFF_DB3 + tid] = db3[tid];

    // ---- prologue: load first batch of 4 images (guarded per image) ----
    {
        const int b0 = blockIdx.x * 4;
        #pragma unroll
        for (int k = 0; k < 4; k++) {
            if (b0 + k < nimg) {
                const float4* iv = reinterpret_cast<const float4*>(inputs + (size_t)(b0 + k) * 784);
                float4* ov = reinterpret_cast<float4*>(sm + OFF_IMG + k * 784);
                for (int i = tid; i < 196; i += 512) ov[i] = iv[i];
            }
        }
    }
    __syncthreads();

    const int h     = tid >> 8;      // half 0/1
    const int t     = tid & 255;     // thread within half
    const int slot0 = h * 2;
    const int qstep = gridDim.x * 4;

    // ---- pipeline prologue: conv1 on the first pair ----
    do_conv1_pair(sm, t, slot0);
    HBAR(h);

    for (int base = blockIdx.x * 4; base < nimg; base += qstep) {
        // P1: conv2(cur) || prefetch(next pair)
        if (t < 128) do_conv2(sm, t, slot0);
        else         do_prefetch(sm, t, slot0, inputs, base + qstep, nimg);
        HBAR(h);

        // P2: conv1(next, already prefetched) || fc chain(cur)
        if (t < 160) {
            do_conv1_pair(sm, t, slot0);     // harmless on stale data past end
        } else {
            const int tF = t - 160;
            do_fc1_96(sm, tF, slot0);
            FBAR(h);
            do_fc2_96(sm, tF, slot0);
            FBAR(h);
            do_fc3_softmax_96(sm, tF, slot0, base + slot0, nimg);
        }
        HBAR(h);
    }
}

// ---------------------------------------------------------------------------
// Kernel 2: Luhn DP (register-resident, high-MLP loads).
// ---------------------------------------------------------------------------
template <int N>
__device__ __forceinline__ float luhn_eval(const float* __restrict__ p)
{
    const int LUHN[10] = {0, 5, 1, 6, 2, 7, 3, 8, 4, 9};
    float4 v[(N * 10) / 4];
    const float4* pv = reinterpret_cast<const float4*>(p);
    #pragma unroll
    for (int i = 0; i < (N * 10) / 4; i++) v[i] = pv[i];
    float d[N * 10];
    #pragma unroll
    for (int i = 0; i < (N * 10) / 4; i++) {
        d[4 * i] = v[i].x; d[4 * i + 1] = v[i].y;
        d[4 * i + 2] = v[i].z; d[4 * i + 3] = v[i].w;
    }
    const int m = N - 1;
    float cur[10];
    #pragma unroll
    for (int j = 0; j < 10; j++)
        cur[j] = ((0 % 2) == (m % 2)) ? d[10 + LUHN[j]] : d[10 + j];
    #pragma unroll
    for (int i = 1; i < m; i++) {
        float dd[10];
        #pragma unroll
        for (int j = 0; j < 10; j++)
            dd[j] = ((i % 2) == (m % 2)) ? d[(i + 1) * 10 + LUHN[j]] : d[(i + 1) * 10 + j];
        float nxt[10];
        #pragma unroll
        for (int s = 0; s < 10; s++) nxt[s] = 0.0f;
        #pragma unroll
        for (int a = 0; a < 10; a++)
            #pragma unroll
            for (int q = 0; q < 10; q++)
                nxt[(a + q) % 10] = fmaf(cur[a], dd[q], nxt[(a + q) % 10]);
        #pragma unroll
        for (int s = 0; s < 10; s++) cur[s] = nxt[s];
    }
    float t10 = 0.0f;
    #pragma unroll
    for (int a = 1; a < 10; a++) t10 = fmaf(d[a], cur[10 - a], t10);
    return logf(t10);
}

__device__ float luhn_generic(const float* __restrict__ p, int n)
{
    const int LUHN[10] = {0, 5, 1, 6, 2, 7, 3, 8, 4, 9};
    const int m = n - 1;
    float cur[10];
    {
        const float* d = p + 10;
        bool perm = ((0 & 1) == (m & 1));
        #pragma unroll
        for (int j = 0; j < 10; j++) cur[j] = perm ? d[LUHN[j]] : d[j];
    }
    for (int i = 1; i < m; i++) {
        const float* d = p + (size_t)(i + 1) * 10;
        bool perm = ((i & 1) == (m & 1));
        float dd[10];
        #pragma unroll
        for (int j = 0; j < 10; j++) dd[j] = perm ? d[LUHN[j]] : d[j];
        float nxt[10];
        #pragma unroll
        for (int s = 0; s < 10; s++) nxt[s] = 0.0f;
        #pragma unroll
        for (int a = 0; a < 10; a++)
            #pragma unroll
            for (int q = 0; q < 10; q++)
                nxt[(a + q) % 10] = fmaf(cur[a], dd[q], nxt[(a + q) % 10]);
        #pragma unroll
        for (int s = 0; s < 10; s++) cur[s] = nxt[s];
    }
    float t10 = 0.0f;
    #pragma unroll
    for (int a = 1; a < 10; a++) t10 = fmaf(p[a], cur[10 - a], t10);
    return logf(t10);
}

__global__ void luhn_kernel(float* __restrict__ out, int B, int n)
{
    int b = blockIdx.x * blockDim.x + threadIdx.x;
    if (b >= B) return;
    const float* p = g_probs + (size_t)b * n * 10;
    if (n == 16) out[b] = luhn_eval<16>(p);
    else         out[b] = luhn_generic(p, n);
}

// ---------------------------------------------------------------------------
extern "C" void kernel_launch(void* const* d_in, const int* in_sizes, int n_in,
                              void* d_out, int out_size)
{
    const float* inputs = (const float*)d_in[0];
    const float* cw1    = (const float*)d_in[1];
    const float* cb1    = (const float*)d_in[2];
    const float* cw2    = (const float*)d_in[3];
    const float* cb2    = (const float*)d_in[4];
    const float* dw1    = (const float*)d_in[5];
    const float* db1    = (const float*)d_in[6];
    const float* dw2    = (const float*)d_in[7];
    const float* db2    = (const float*)d_in[8];
    const float* dw3    = (const float*)d_in[9];
    const float* db3    = (const float*)d_in[10];
    float* out = (float*)d_out;

    const int B = out_size;                      // 1024
    const int n = in_sizes[0] / (B * 784);       // 16
    const int nimg = B * n;

    const size_t smem_bytes = SMEM_FLOATS * sizeof(float);  // 229,136 B
    cudaFuncSetAttribute(cnn_kernel, cudaFuncAttributeMaxDynamicSharedMemorySize,
                         (int)smem_bytes);

    cnn_kernel<<<148, 512, smem_bytes>>>(inputs, cw1, cb1, cw2, cb2,
                                         dw1, db1, dw2, db2, dw3, db3, nimg);
    luhn_kernel<<<(B + 127) / 128, 128>>>(out, B, n);
}